// round 14
// baseline (speedup 1.0000x reference)
#include <cuda_runtime.h>
#include <cuda_fp16.h>
#include <math.h>
#include <stdint.h>

#define T_TOK 1024
#define H_DIM 1024
#define E_NUM 32
#define I_DIM 512
#define IS_DIM 2048
#define NGROUP 8
#define GSIZE 4
#define TOPKG 4
#define TOPK 8
#define RSCALE 2.5f

// Scratch: activations stored as fp16
__device__ __half g_xh[(size_t)T_TOK * H_DIM];
__device__ __half g_act[(size_t)E_NUM * T_TOK * I_DIM];
__device__ __half g_sact[(size_t)T_TOK * IS_DIM];
__device__ float g_dact[(size_t)E_NUM * T_TOK * H_DIM];   // routed down staging
__device__ float g_sds[4][(size_t)T_TOK * H_DIM];         // shared split-K staging
__device__ int   g_cnt[E_NUM];
__device__ int   g_tok[E_NUM * T_TOK];
__device__ float g_wgt[E_NUM * T_TOK];
__device__ int   g_pos[T_TOK * TOPK];

__device__ __forceinline__ float silu_f(float v) { return v / (1.f + expf(-v)); }

__device__ __forceinline__ uint32_t h2pack(float a, float b) {
    __half2 h = __floats2half2_rn(a, b);
    return *reinterpret_cast<uint32_t*>(&h);
}

__device__ __forceinline__ uint32_t smem_u32(const void* p) {
    uint32_t a;
    asm("{ .reg .u64 t; cvta.to.shared.u64 t, %1; cvt.u32.u64 %0, t; }" : "=r"(a) : "l"(p));
    return a;
}

__device__ __forceinline__ void mma_f16(float* c,
                                        uint32_t a0, uint32_t a1, uint32_t a2, uint32_t a3,
                                        uint32_t b0, uint32_t b1)
{
    asm volatile(
        "mma.sync.aligned.m16n8k16.row.col.f32.f16.f16.f32 "
        "{%0,%1,%2,%3}, {%4,%5,%6,%7}, {%8,%9}, {%0,%1,%2,%3};\n"
        : "+f"(c[0]), "+f"(c[1]), "+f"(c[2]), "+f"(c[3])
        : "r"(a0), "r"(a1), "r"(a2), "r"(a3), "r"(b0), "r"(b1));
}

__device__ __forceinline__ void ldm_x4(uint32_t* r, uint32_t addr) {
    asm volatile("ldmatrix.sync.aligned.m8n8.x4.shared.b16 {%0,%1,%2,%3}, [%4];"
        : "=r"(r[0]), "=r"(r[1]), "=r"(r[2]), "=r"(r[3]) : "r"(addr));
}

#define CP16(dst, src, sz) \
    asm volatile("cp.async.cg.shared.global [%0], [%1], 16, %2;" \
                 :: "r"(dst), "l"(src), "r"(sz) : "memory")
#define CP_COMMIT() asm volatile("cp.async.commit_group;" ::: "memory")
#define CP_WAIT0()  asm volatile("cp.async.wait_group 0;" ::: "memory")

// zero expert counters
__global__ void k_zero() {
    if (threadIdx.x < E_NUM) g_cnt[threadIdx.x] = 0;
}

// ---------------------------------------------------------------------------
// Gate GEMV + routing + gather; also converts this token's x row to fp16
// ---------------------------------------------------------------------------
__global__ __launch_bounds__(256) void k_gate_route(
    const float* __restrict__ x,
    const float* __restrict__ gate_w,
    const float* __restrict__ e_bias)
{
    __shared__ float s_logit[E_NUM];
    const int t = blockIdx.x;
    const int warp = threadIdx.x >> 5, lane = threadIdx.x & 31;
    const float* xr = x + (size_t)t * H_DIM;
    {
        float4 v = ((const float4*)xr)[threadIdx.x];
        ((uint2*)(g_xh + (size_t)t * H_DIM))[threadIdx.x] =
            make_uint2(h2pack(v.x, v.y), h2pack(v.z, v.w));
    }
    for (int e = warp; e < E_NUM; e += 8) {
        const float* gw = gate_w + (size_t)e * H_DIM;
        float s = 0.f;
        for (int k = lane; k < H_DIM; k += 32) s += xr[k] * gw[k];
        #pragma unroll
        for (int o = 16; o; o >>= 1) s += __shfl_xor_sync(0xffffffffu, s, o);
        if (lane == 0) s_logit[e] = s;
    }
    __syncthreads();
    if (threadIdx.x != 0) return;

    float scores[E_NUM], swb[E_NUM];
    for (int e = 0; e < E_NUM; e++) {
        float sc = 1.f / (1.f + expf(-s_logit[e]));
        scores[e] = sc;
        swb[e] = sc + e_bias[e];
    }
    float gs[NGROUP];
    for (int g = 0; g < NGROUP; g++) {
        float m1 = -1e30f, m2 = -1e30f;
        for (int j = 0; j < GSIZE; j++) {
            float v = swb[g * GSIZE + j];
            if (v > m1) { m2 = m1; m1 = v; }
            else if (v > m2) m2 = v;
        }
        gs[g] = m1 + m2;
    }
    bool gsel[NGROUP] = {false};
    for (int it = 0; it < TOPKG; it++) {
        int bi = 0; float bv = -1e30f;
        for (int g = 0; g < NGROUP; g++)
            if (!gsel[g] && gs[g] > bv) { bv = gs[g]; bi = g; }
        gsel[bi] = true;
    }
    float val[E_NUM];
    for (int e = 0; e < E_NUM; e++) val[e] = gsel[e / GSIZE] ? swb[e] : 0.f;
    bool taken[E_NUM] = {false};
    int sel[TOPK];
    float denom = 0.f;
    for (int it = 0; it < TOPK; it++) {
        int bi = 0; float bv = -1e30f;
        for (int e = 0; e < E_NUM; e++)
            if (!taken[e] && val[e] > bv) { bv = val[e]; bi = e; }
        taken[bi] = true; sel[it] = bi; denom += scores[bi];
    }
    float inv = RSCALE / (denom + 1e-20f);
    for (int it = 0; it < TOPK; it++) {
        int e = sel[it];
        int slot = atomicAdd(&g_cnt[e], 1);
        g_tok[e * T_TOK + slot] = t;
        g_wgt[e * T_TOK + slot] = scores[e] * inv;
        g_pos[t * TOPK + it] = e * T_TOK + slot;
    }
}

// ---------------------------------------------------------------------------
// DUAL smem stage (words), BK=32:
//   A fp16 128x20 @0 | Bg fp32 32x64 swizzled @2560 | Bu @4608
// Stage = 6656 w = 26624 B; 2 stages = 53248 B (2 CTAs/SM, 256 thr).
// DOWN smem stage: A fp16 128x20 @0 | B fp32 32x64 swizzled @2560
// Stage = 4608 w = 18432 B; 2 stages = 36864 B (4 CTAs/SM, 128 thr).
// B swizzle: phys_chunk = bc ^ (((bk>>1)&3)<<1).
// ---------------------------------------------------------------------------
#define DUAL_STAGE_W 6656
#define DUAL_STAGE_B 26624
#define DUAL_SMEM (2 * DUAL_STAGE_B)
#define DOWN_STAGE_W 4608
#define DOWN_STAGE_B 18432
#define DOWN_SMEM (2 * DOWN_STAGE_B)

// ---------------------------------------------------------------------------
// Dual fp16 MMA GEMM, warp-specialized: 256 thr, warps 0-3 gate, 4-7 up.
// Block 128x64, BK=32, per-group 2m x 2n warps of 64x32, acc=64/thread.
// Epilogue: gate acc -> smem exchange -> up warps fuse silu(g)*u*wgt.
// ---------------------------------------------------------------------------
__global__ __launch_bounds__(256, 2)
void k_dual(const float* __restrict__ w_gate,
            const float* __restrict__ w_up,
            const float* __restrict__ ws_gate,
            const float* __restrict__ ws_up)
{
    extern __shared__ uint32_t sm[];
    const int z = blockIdx.z;
    const bool routed = z < E_NUM;
    const int e = routed ? z : 0;
    const int M = routed ? g_cnt[e] : T_TOK;
    const int m0 = blockIdx.y * 128;
    if (m0 >= M) return;
    const int NS = routed ? I_DIM : IS_DIM;
    const int n0 = routed ? blockIdx.x * 64
                          : (z - E_NUM) * 512 + blockIdx.x * 64;
    const float* __restrict__ Wg = routed ? w_gate + (size_t)e * H_DIM * I_DIM : ws_gate;
    const float* __restrict__ Wu = routed ? w_up   + (size_t)e * H_DIM * I_DIM : ws_up;
    __half* __restrict__ Act = routed ? g_act + (size_t)e * T_TOK * I_DIM : g_sact;

    const uint32_t sb = smem_u32(sm);
    const int tid = threadIdx.x;
    const int warp = tid >> 5, lane = tid & 31;
    const int wg = warp >> 2;            // 0 = gate, 1 = up
    const int w4 = warp & 3;
    const int wm = w4 & 1, wn = w4 >> 1;
    const int grp = lane >> 2, tg = lane & 3;

    // A cp.async: 512 units, 2/thread
    const __half* aSrc[2];
    uint32_t aDst[2], aSz[2];
    #pragma unroll
    for (int u = 0; u < 2; u++) {
        int idx = tid + u * 256;
        int am = idx >> 2, ak = idx & 3;
        int gm = m0 + am;
        bool ok = gm < M;
        int srow = ok ? (routed ? g_tok[e * T_TOK + gm] : gm) : 0;
        aSrc[u] = g_xh + (size_t)srow * H_DIM + ak * 8;
        aDst[u] = (uint32_t)(am * 80 + ak * 16);
        aSz[u] = ok ? 16u : 0u;
    }
    // B cp.async fp32: per matrix 512 units, 2/thread/matrix
    const float* gSrc[2];
    const float* uSrc[2];
    uint32_t bDst[2];
    #pragma unroll
    for (int u = 0; u < 2; u++) {
        int idx = tid + u * 256;
        int bk = idx >> 4, bc = idx & 15;
        int cph = bc ^ (((bk >> 1) & 3) << 1);
        gSrc[u] = Wg + (size_t)bk * NS + n0 + bc * 4;
        uSrc[u] = Wu + (size_t)bk * NS + n0 + bc * 4;
        bDst[u] = (uint32_t)((2560 + bk * 64 + cph * 4) * 4);
    }

    uint32_t lmoff[4];
    {
        int lr = (lane & 7) + ((lane >> 3) & 1) * 8;
        int lk = lane >> 4;
        #pragma unroll
        for (int mi = 0; mi < 4; mi++)
            lmoff[mi] = (uint32_t)((wm * 64 + mi * 16 + lr) * 80 + lk * 16);
    }
    // B fragment offsets: this warp group's matrix (gate @2560, up @4608)
    int bwv[4];
    #pragma unroll
    for (int ni = 0; ni < 4; ni++) {
        int n = wn * 32 + ni * 8 + grp;
        int cph = (n >> 2) ^ (tg << 1);
        bwv[ni] = 2560 + wg * 2048 + tg * 128 + cph * 4 + (n & 3);
    }

    const int NC = H_DIM / 32;  // 32
    #pragma unroll
    for (int u = 0; u < 2; u++) {
        CP16(sb + aDst[u], aSrc[u], aSz[u]);
        CP16(sb + bDst[u],        gSrc[u], 16u);
        CP16(sb + bDst[u] + 8192, uSrc[u], 16u);
    }
    CP_COMMIT();

    float acc[4][4][4];
    #pragma unroll
    for (int mi = 0; mi < 4; mi++)
        #pragma unroll
        for (int ni = 0; ni < 4; ni++)
            #pragma unroll
            for (int q = 0; q < 4; q++) acc[mi][ni][q] = 0.f;

    for (int c = 0; c < NC; c++) {
        CP_WAIT0();
        __syncthreads();
        if (c + 1 < NC) {
            int c1 = c + 1;
            uint32_t st = sb + (c1 & 1) * DUAL_STAGE_B;
            #pragma unroll
            for (int u = 0; u < 2; u++) {
                CP16(st + aDst[u], aSrc[u] + c1 * 32, aSz[u]);
                CP16(st + bDst[u],        gSrc[u] + (size_t)c1 * 32 * NS, 16u);
                CP16(st + bDst[u] + 8192, uSrc[u] + (size_t)c1 * 32 * NS, 16u);
            }
            CP_COMMIT();
        }
        const uint32_t sbase = sb + (c & 1) * DUAL_STAGE_B;
        const float* Sf = (const float*)(sm + (c & 1) * DUAL_STAGE_W);
        #pragma unroll
        for (int ks = 0; ks < 2; ks++) {
            uint32_t af[4][4];
            #pragma unroll
            for (int mi = 0; mi < 4; mi++)
                ldm_x4(af[mi], sbase + lmoff[mi] + ks * 32);
            #pragma unroll
            for (int ni = 0; ni < 4; ni++) {
                const int w = bwv[ni] + ks * 1024;
                uint32_t b0 = h2pack(Sf[w],       Sf[w + 64]);
                uint32_t b1 = h2pack(Sf[w + 512], Sf[w + 576]);
                #pragma unroll
                for (int mi = 0; mi < 4; mi++)
                    mma_f16(acc[mi][ni], af[mi][0], af[mi][1], af[mi][2], af[mi][3], b0, b1);
            }
        }
    }

    // -------- epilogue: exchange gate acc through smem, up warps fuse --------
    float* ex = (float*)sm;   // 128 x 66 floats = 33792 B (stage area is dead)
    __syncthreads();
    if (wg == 0) {
        #pragma unroll
        for (int mi = 0; mi < 4; mi++) {
            int r0 = wm * 64 + mi * 16 + grp;
            #pragma unroll
            for (int ni = 0; ni < 4; ni++) {
                int col = wn * 32 + ni * 8 + tg * 2;
                ex[r0 * 66 + col]       = acc[mi][ni][0];
                ex[r0 * 66 + col + 1]   = acc[mi][ni][1];
                ex[(r0 + 8) * 66 + col]     = acc[mi][ni][2];
                ex[(r0 + 8) * 66 + col + 1] = acc[mi][ni][3];
            }
        }
    }
    __syncthreads();
    if (wg == 1) {
        #pragma unroll
        for (int mi = 0; mi < 4; mi++) {
            int lr0 = wm * 64 + mi * 16 + grp;
            int r0 = m0 + lr0;
            int r1 = r0 + 8;
            float w0 = 1.f, w1 = 1.f;
            if (routed) {
                if (r0 < M) w0 = g_wgt[e * T_TOK + r0];
                if (r1 < M) w1 = g_wgt[e * T_TOK + r1];
            }
            #pragma unroll
            for (int ni = 0; ni < 4; ni++) {
                int lcol = wn * 32 + ni * 8 + tg * 2;
                int col = n0 + lcol;
                if (r0 < M) {
                    float g0 = ex[lr0 * 66 + lcol];
                    float g1 = ex[lr0 * 66 + lcol + 1];
                    uint32_t v = h2pack(silu_f(g0) * acc[mi][ni][0] * w0,
                                        silu_f(g1) * acc[mi][ni][1] * w0);
                    *(uint32_t*)(Act + (size_t)r0 * NS + col) = v;
                }
                if (r1 < M) {
                    float g2 = ex[(lr0 + 8) * 66 + lcol];
                    float g3 = ex[(lr0 + 8) * 66 + lcol + 1];
                    uint32_t v = h2pack(silu_f(g2) * acc[mi][ni][2] * w1,
                                        silu_f(g3) * acc[mi][ni][3] * w1);
                    *(uint32_t*)(Act + (size_t)r1 * NS + col) = v;
                }
            }
        }
    }
}

// ---------------------------------------------------------------------------
// Down-proj fp16 MMA (exact R13): N-tile 64, 4 CTAs/SM.
// Block 128x64, BK=32, 4 warps (2m x 2n), warp 64x32, ldmatrix A, acc=64.
// ---------------------------------------------------------------------------
__global__ __launch_bounds__(128, 4)
void k_down(const float* __restrict__ w_down,
            const float* __restrict__ ws_down)
{
    extern __shared__ uint32_t sm[];
    const int z = blockIdx.z;
    const bool routed = z < E_NUM;
    const int e = routed ? z : 0;
    const int M = routed ? g_cnt[e] : T_TOK;
    const int m0 = blockIdx.y * 128;
    if (m0 >= M) return;
    const int n0 = blockIdx.x * 64;
    const int koff = routed ? 0 : (z - E_NUM) * 512;
    const __half* __restrict__ A = routed ? g_act + (size_t)e * T_TOK * I_DIM : g_sact;
    const int AS = routed ? I_DIM : IS_DIM;
    const float* __restrict__ B = routed ? w_down + (size_t)e * I_DIM * H_DIM
                                         : ws_down + (size_t)koff * H_DIM;
    float* __restrict__ Dst = routed ? g_dact + (size_t)e * T_TOK * H_DIM
                                     : g_sds[z - E_NUM];
    const int N = H_DIM;

    const uint32_t sb = smem_u32(sm);
    const int tid = threadIdx.x;
    const int warp = tid >> 5, lane = tid & 31;
    const int wm = warp & 1, wn = warp >> 1;
    const int grp = lane >> 2, tg = lane & 3;

    const __half* aSrc[4];
    uint32_t aDst[4], aSz[4];
    #pragma unroll
    for (int u = 0; u < 4; u++) {
        int idx = tid + u * 128;
        int am = idx >> 2, ak = idx & 3;
        int gm = m0 + am;
        bool ok = gm < M;
        aSrc[u] = A + (size_t)(ok ? gm : 0) * AS + koff + ak * 8;
        aDst[u] = (uint32_t)(am * 80 + ak * 16);
        aSz[u] = ok ? 16u : 0u;
    }
    const float* bSrc[4];
    uint32_t bDst[4];
    #pragma unroll
    for (int u = 0; u < 4; u++) {
        int idx = tid + u * 128;
        int bk = idx >> 4, bc = idx & 15;
        int cph = bc ^ (((bk >> 1) & 3) << 1);
        bSrc[u] = B + (size_t)bk * N + n0 + bc * 4;
        bDst[u] = (uint32_t)((2560 + bk * 64 + cph * 4) * 4);
    }

    uint32_t lmoff[4];
    {
        int lr = (lane & 7) + ((lane >> 3) & 1) * 8;
        int lk = lane >> 4;
        #pragma unroll
        for (int mi = 0; mi < 4; mi++)
            lmoff[mi] = (uint32_t)((wm * 64 + mi * 16 + lr) * 80 + lk * 16);
    }
    int bwv[4];
    #pragma unroll
    for (int ni = 0; ni < 4; ni++) {
        int n = wn * 32 + ni * 8 + grp;
        int cph = (n >> 2) ^ (tg << 1);
        bwv[ni] = 2560 + tg * 128 + cph * 4 + (n & 3);
    }

    const int NC = 512 / 32;  // 16
    #pragma unroll
    for (int u = 0; u < 4; u++) {
        CP16(sb + aDst[u], aSrc[u], aSz[u]);
        CP16(sb + bDst[u], bSrc[u], 16u);
    }
    CP_COMMIT();

    float acc[4][4][4];
    #pragma unroll
    for (int mi = 0; mi < 4; mi++)
        #pragma unroll
        for (int ni = 0; ni < 4; ni++)
            #pragma unroll
            for (int q = 0; q < 4; q++) acc[mi][ni][q] = 0.f;

    for (int c = 0; c < NC; c++) {
        CP_WAIT0();
        __syncthreads();
        if (c + 1 < NC) {
            int c1 = c + 1;
            uint32_t st = sb + (c1 & 1) * DOWN_STAGE_B;
            #pragma unroll
            for (int u = 0; u < 4; u++) {
                CP16(st + aDst[u], aSrc[u] + c1 * 32, aSz[u]);
                CP16(st + bDst[u], bSrc[u] + (size_t)c1 * 32 * N, 16u);
            }
            CP_COMMIT();
        }
        const uint32_t sbase = sb + (c & 1) * DOWN_STAGE_B;
        const float* Sf = (const float*)(sm + (c & 1) * DOWN_STAGE_W);
        #pragma unroll
        for (int ks = 0; ks < 2; ks++) {
            uint32_t af[4][4];
            #pragma unroll
            for (int mi = 0; mi < 4; mi++)
                ldm_x4(af[mi], sbase + lmoff[mi] + ks * 32);
            #pragma unroll
            for (int ni = 0; ni < 4; ni++) {
                const int w = bwv[ni] + ks * 1024;
                uint32_t b0 = h2pack(Sf[w],       Sf[w + 64]);
                uint32_t b1 = h2pack(Sf[w + 512], Sf[w + 576]);
                #pragma unroll
                for (int mi = 0; mi < 4; mi++)
                    mma_f16(acc[mi][ni], af[mi][0], af[mi][1], af[mi][2], af[mi][3], b0, b1);
            }
        }
    }

    #pragma unroll
    for (int mi = 0; mi < 4; mi++) {
        int r0 = m0 + wm * 64 + mi * 16 + grp;
        int r1 = r0 + 8;
        bool ok0 = r0 < M, ok1 = r1 < M;
        #pragma unroll
        for (int ni = 0; ni < 4; ni++) {
            int col = n0 + wn * 32 + ni * 8 + tg * 2;
            if (ok0) {
                float2 v = make_float2(acc[mi][ni][0], acc[mi][ni][1]);
                *(float2*)(Dst + (size_t)r0 * N + col) = v;
            }
            if (ok1) {
                float2 v = make_float2(acc[mi][ni][2], acc[mi][ni][3]);
                *(float2*)(Dst + (size_t)r1 * N + col) = v;
            }
        }
    }
}

// ---------------------------------------------------------------------------
// Final gather-reduce: out[t] = sum_{i<8} g_dact[pos_i] + sum_{s<4} g_sds[s][t]
// ---------------------------------------------------------------------------
__global__ __launch_bounds__(256) void k_reduce(float* __restrict__ out) {
    __shared__ int pos[TOPK];
    const int t = blockIdx.x;
    if (threadIdx.x < TOPK) pos[threadIdx.x] = g_pos[t * TOPK + threadIdx.x];
    __syncthreads();
    const int h = threadIdx.x * 4;
    float4 s = *(const float4*)(&g_sds[0][(size_t)t * H_DIM + h]);
    #pragma unroll
    for (int q = 1; q < 4; q++) {
        float4 v = *(const float4*)(&g_sds[q][(size_t)t * H_DIM + h]);
        s.x += v.x; s.y += v.y; s.z += v.z; s.w += v.w;
    }
    #pragma unroll
    for (int i = 0; i < TOPK; i++) {
        float4 v = *(const float4*)(g_dact + (size_t)pos[i] * H_DIM + h);
        s.x += v.x; s.y += v.y; s.z += v.z; s.w += v.w;
    }
    *(float4*)(out + (size_t)t * H_DIM + h) = s;
}

// ---------------------------------------------------------------------------
extern "C" void kernel_launch(void* const* d_in, const int* in_sizes, int n_in,
                              void* d_out, int out_size)
{
    const float* x       = (const float*)d_in[0];
    const float* gate_w  = (const float*)d_in[1];
    const float* e_bias  = (const float*)d_in[2];
    const float* w_gate  = (const float*)d_in[3];
    const float* w_up    = (const float*)d_in[4];
    const float* w_down  = (const float*)d_in[5];
    const float* ws_gate = (const float*)d_in[6];
    const float* ws_up   = (const float*)d_in[7];
    const float* ws_down = (const float*)d_in[8];
    float* out = (float*)d_out;

    static bool attr_done = false;
    if (!attr_done) {
        cudaFuncSetAttribute(k_dual, cudaFuncAttributeMaxDynamicSharedMemorySize, DUAL_SMEM);
        cudaFuncSetAttribute(k_down, cudaFuncAttributeMaxDynamicSharedMemorySize, DOWN_SMEM);
        attr_done = true;
    }

    k_zero<<<1, 32>>>();
    k_gate_route<<<T_TOK, 256>>>(x, gate_w, e_bias);
    // dual GEMMs (warp-specialized): routed z=0..31, shared z=32..35
    k_dual<<<dim3(8, 8, E_NUM + 4), 256, DUAL_SMEM>>>(w_gate, w_up, ws_gate, ws_up);
    // down GEMMs: N-tile 64, routed z=0..31, shared split-K z=32..35
    k_down<<<dim3(16, 8, E_NUM + 4), 128, DOWN_SMEM>>>(w_down, ws_down);
    k_reduce<<<T_TOK, 256>>>(out);
}

// round 15
// speedup vs baseline: 1.0373x; 1.0373x over previous
#include <cuda_runtime.h>
#include <cuda_fp16.h>
#include <math.h>
#include <stdint.h>

#define T_TOK 1024
#define H_DIM 1024
#define E_NUM 32
#define I_DIM 512
#define IS_DIM 2048
#define NGROUP 8
#define GSIZE 4
#define TOPKG 4
#define TOPK 8
#define RSCALE 2.5f

// Scratch: activations stored as fp16
__device__ __half g_xh[(size_t)T_TOK * H_DIM];
__device__ __half g_act[(size_t)E_NUM * T_TOK * I_DIM];
__device__ __half g_sact[(size_t)T_TOK * IS_DIM];
__device__ float g_dact[(size_t)E_NUM * T_TOK * H_DIM];   // routed down staging
__device__ float g_sds[4][(size_t)T_TOK * H_DIM];         // shared split-K staging
__device__ int   g_cnt[E_NUM];
__device__ int   g_tok[E_NUM * T_TOK];
__device__ float g_wgt[E_NUM * T_TOK];
__device__ int   g_pos[T_TOK * TOPK];

__device__ __forceinline__ float silu_f(float v) { return v / (1.f + expf(-v)); }

__device__ __forceinline__ uint32_t h2pack(float a, float b) {
    __half2 h = __floats2half2_rn(a, b);
    return *reinterpret_cast<uint32_t*>(&h);
}

__device__ __forceinline__ uint32_t smem_u32(const void* p) {
    uint32_t a;
    asm("{ .reg .u64 t; cvta.to.shared.u64 t, %1; cvt.u32.u64 %0, t; }" : "=r"(a) : "l"(p));
    return a;
}

__device__ __forceinline__ void mma_f16(float* c,
                                        uint32_t a0, uint32_t a1, uint32_t a2, uint32_t a3,
                                        uint32_t b0, uint32_t b1)
{
    asm volatile(
        "mma.sync.aligned.m16n8k16.row.col.f32.f16.f16.f32 "
        "{%0,%1,%2,%3}, {%4,%5,%6,%7}, {%8,%9}, {%0,%1,%2,%3};\n"
        : "+f"(c[0]), "+f"(c[1]), "+f"(c[2]), "+f"(c[3])
        : "r"(a0), "r"(a1), "r"(a2), "r"(a3), "r"(b0), "r"(b1));
}

__device__ __forceinline__ void ldm_x4(uint32_t* r, uint32_t addr) {
    asm volatile("ldmatrix.sync.aligned.m8n8.x4.shared.b16 {%0,%1,%2,%3}, [%4];"
        : "=r"(r[0]), "=r"(r[1]), "=r"(r[2]), "=r"(r[3]) : "r"(addr));
}

__device__ __forceinline__ void ldm_x4t(uint32_t* r, uint32_t addr) {
    asm volatile("ldmatrix.sync.aligned.m8n8.x4.trans.shared.b16 {%0,%1,%2,%3}, [%4];"
        : "=r"(r[0]), "=r"(r[1]), "=r"(r[2]), "=r"(r[3]) : "r"(addr));
}

#define CP16(dst, src, sz) \
    asm volatile("cp.async.cg.shared.global [%0], [%1], 16, %2;" \
                 :: "r"(dst), "l"(src), "r"(sz) : "memory")
#define CP_COMMIT() asm volatile("cp.async.commit_group;" ::: "memory")
#define CP_WAIT0()  asm volatile("cp.async.wait_group 0;" ::: "memory")

// zero expert counters
__global__ void k_zero() {
    if (threadIdx.x < E_NUM) g_cnt[threadIdx.x] = 0;
}

// ---------------------------------------------------------------------------
// Gate GEMV + routing + gather; also converts this token's x row to fp16
// ---------------------------------------------------------------------------
__global__ __launch_bounds__(256) void k_gate_route(
    const float* __restrict__ x,
    const float* __restrict__ gate_w,
    const float* __restrict__ e_bias)
{
    __shared__ float s_logit[E_NUM];
    const int t = blockIdx.x;
    const int warp = threadIdx.x >> 5, lane = threadIdx.x & 31;
    const float* xr = x + (size_t)t * H_DIM;
    {
        float4 v = ((const float4*)xr)[threadIdx.x];
        ((uint2*)(g_xh + (size_t)t * H_DIM))[threadIdx.x] =
            make_uint2(h2pack(v.x, v.y), h2pack(v.z, v.w));
    }
    for (int e = warp; e < E_NUM; e += 8) {
        const float* gw = gate_w + (size_t)e * H_DIM;
        float s = 0.f;
        for (int k = lane; k < H_DIM; k += 32) s += xr[k] * gw[k];
        #pragma unroll
        for (int o = 16; o; o >>= 1) s += __shfl_xor_sync(0xffffffffu, s, o);
        if (lane == 0) s_logit[e] = s;
    }
    __syncthreads();
    if (threadIdx.x != 0) return;

    float scores[E_NUM], swb[E_NUM];
    for (int e = 0; e < E_NUM; e++) {
        float sc = 1.f / (1.f + expf(-s_logit[e]));
        scores[e] = sc;
        swb[e] = sc + e_bias[e];
    }
    float gs[NGROUP];
    for (int g = 0; g < NGROUP; g++) {
        float m1 = -1e30f, m2 = -1e30f;
        for (int j = 0; j < GSIZE; j++) {
            float v = swb[g * GSIZE + j];
            if (v > m1) { m2 = m1; m1 = v; }
            else if (v > m2) m2 = v;
        }
        gs[g] = m1 + m2;
    }
    bool gsel[NGROUP] = {false};
    for (int it = 0; it < TOPKG; it++) {
        int bi = 0; float bv = -1e30f;
        for (int g = 0; g < NGROUP; g++)
            if (!gsel[g] && gs[g] > bv) { bv = gs[g]; bi = g; }
        gsel[bi] = true;
    }
    float val[E_NUM];
    for (int e = 0; e < E_NUM; e++) val[e] = gsel[e / GSIZE] ? swb[e] : 0.f;
    bool taken[E_NUM] = {false};
    int sel[TOPK];
    float denom = 0.f;
    for (int it = 0; it < TOPK; it++) {
        int bi = 0; float bv = -1e30f;
        for (int e = 0; e < E_NUM; e++)
            if (!taken[e] && val[e] > bv) { bv = val[e]; bi = e; }
        taken[bi] = true; sel[it] = bi; denom += scores[bi];
    }
    float inv = RSCALE / (denom + 1e-20f);
    for (int it = 0; it < TOPK; it++) {
        int e = sel[it];
        int slot = atomicAdd(&g_cnt[e], 1);
        g_tok[e * T_TOK + slot] = t;
        g_wgt[e * T_TOK + slot] = scores[e] * inv;
        g_pos[t * TOPK + it] = e * T_TOK + slot;
    }
}

// ---------------------------------------------------------------------------
// DUAL smem stage (words), BK=32 (exact R13):
//   A fp16 128x20 @0 | Bg fp32 32x64 swizzled @2560 | Bu @4608
// Stage = 6656 w = 26624 B; 2 stages (3 CTAs/SM).
// DOWN stage (bytes): A fp16 128 rows x 80B = 10240 | B fp16 [k][n] 32 rows
//   x 144B (128 data + 16 pad) @10240 -> stage 14848 B; 2 stages (4 CTAs/SM).
// ---------------------------------------------------------------------------
#define DUAL_STAGE_W 6656
#define DUAL_STAGE_B 26624
#define DUAL_SMEM (2 * DUAL_STAGE_B)
#define DOWN_STAGE_B 14848
#define DOWN_SMEM (2 * DOWN_STAGE_B)

// ---------------------------------------------------------------------------
// Dual fp16 MMA GEMM (exact R13): act = silu(X@Wg)*(X@Wu) [* combine]
// Block 128x64, BK=32, 4 warps (2m x 2n), warp 64x32 dual, ldmatrix A.
// ---------------------------------------------------------------------------
__global__ __launch_bounds__(128, 3)
void k_dual(const float* __restrict__ w_gate,
            const float* __restrict__ w_up,
            const float* __restrict__ ws_gate,
            const float* __restrict__ ws_up)
{
    extern __shared__ uint32_t sm[];
    const int z = blockIdx.z;
    const bool routed = z < E_NUM;
    const int e = routed ? z : 0;
    const int M = routed ? g_cnt[e] : T_TOK;
    const int m0 = blockIdx.y * 128;
    if (m0 >= M) return;
    const int NS = routed ? I_DIM : IS_DIM;
    const int n0 = routed ? blockIdx.x * 64
                          : (z - E_NUM) * 512 + blockIdx.x * 64;
    const float* __restrict__ Wg = routed ? w_gate + (size_t)e * H_DIM * I_DIM : ws_gate;
    const float* __restrict__ Wu = routed ? w_up   + (size_t)e * H_DIM * I_DIM : ws_up;
    __half* __restrict__ Act = routed ? g_act + (size_t)e * T_TOK * I_DIM : g_sact;

    const uint32_t sb = smem_u32(sm);
    const int tid = threadIdx.x;
    const int warp = tid >> 5, lane = tid & 31;
    const int wm = warp & 1, wn = warp >> 1;
    const int grp = lane >> 2, tg = lane & 3;

    const __half* aSrc[4];
    uint32_t aDst[4], aSz[4];
    #pragma unroll
    for (int u = 0; u < 4; u++) {
        int idx = tid + u * 128;
        int am = idx >> 2, ak = idx & 3;
        int gm = m0 + am;
        bool ok = gm < M;
        int srow = ok ? (routed ? g_tok[e * T_TOK + gm] : gm) : 0;
        aSrc[u] = g_xh + (size_t)srow * H_DIM + ak * 8;
        aDst[u] = (uint32_t)(am * 80 + ak * 16);
        aSz[u] = ok ? 16u : 0u;
    }
    const float* gSrc[4];
    const float* uSrc[4];
    uint32_t bDst[4];
    #pragma unroll
    for (int u = 0; u < 4; u++) {
        int idx = tid + u * 128;
        int bk = idx >> 4, bc = idx & 15;
        int cph = bc ^ (((bk >> 1) & 3) << 1);
        gSrc[u] = Wg + (size_t)bk * NS + n0 + bc * 4;
        uSrc[u] = Wu + (size_t)bk * NS + n0 + bc * 4;
        bDst[u] = (uint32_t)((2560 + bk * 64 + cph * 4) * 4);
    }

    uint32_t lmoff[4];
    {
        int lr = (lane & 7) + ((lane >> 3) & 1) * 8;
        int lk = lane >> 4;
        #pragma unroll
        for (int mi = 0; mi < 4; mi++)
            lmoff[mi] = (uint32_t)((wm * 64 + mi * 16 + lr) * 80 + lk * 16);
    }
    int bwv[4];
    #pragma unroll
    for (int ni = 0; ni < 4; ni++) {
        int n = wn * 32 + ni * 8 + grp;
        int cph = (n >> 2) ^ (tg << 1);
        bwv[ni] = 2560 + tg * 128 + cph * 4 + (n & 3);
    }

    const int NC = H_DIM / 32;  // 32
    #pragma unroll
    for (int u = 0; u < 4; u++) {
        CP16(sb + aDst[u], aSrc[u], aSz[u]);
        CP16(sb + bDst[u],        gSrc[u], 16u);
        CP16(sb + bDst[u] + 8192, uSrc[u], 16u);
    }
    CP_COMMIT();

    float cg[4][4][4], cu[4][4][4];
    #pragma unroll
    for (int mi = 0; mi < 4; mi++)
        #pragma unroll
        for (int ni = 0; ni < 4; ni++)
            #pragma unroll
            for (int q = 0; q < 4; q++) { cg[mi][ni][q] = 0.f; cu[mi][ni][q] = 0.f; }

    for (int c = 0; c < NC; c++) {
        CP_WAIT0();
        __syncthreads();
        if (c + 1 < NC) {
            int c1 = c + 1;
            uint32_t st = sb + (c1 & 1) * DUAL_STAGE_B;
            #pragma unroll
            for (int u = 0; u < 4; u++) {
                CP16(st + aDst[u], aSrc[u] + c1 * 32, aSz[u]);
                CP16(st + bDst[u],        gSrc[u] + (size_t)c1 * 32 * NS, 16u);
                CP16(st + bDst[u] + 8192, uSrc[u] + (size_t)c1 * 32 * NS, 16u);
            }
            CP_COMMIT();
        }
        const uint32_t sbase = sb + (c & 1) * DUAL_STAGE_B;
        const float* Sf = (const float*)(sm + (c & 1) * DUAL_STAGE_W);
        #pragma unroll
        for (int ks = 0; ks < 2; ks++) {
            uint32_t af[4][4];
            #pragma unroll
            for (int mi = 0; mi < 4; mi++)
                ldm_x4(af[mi], sbase + lmoff[mi] + ks * 32);
            #pragma unroll
            for (int ni = 0; ni < 4; ni++) {
                const int w = bwv[ni] + ks * 1024;
                uint32_t bg0 = h2pack(Sf[w],        Sf[w + 64]);
                uint32_t bg1 = h2pack(Sf[w + 512],  Sf[w + 576]);
                uint32_t bu0 = h2pack(Sf[w + 2048], Sf[w + 2112]);
                uint32_t bu1 = h2pack(Sf[w + 2560], Sf[w + 2624]);
                #pragma unroll
                for (int mi = 0; mi < 4; mi++) {
                    mma_f16(cg[mi][ni], af[mi][0], af[mi][1], af[mi][2], af[mi][3], bg0, bg1);
                    mma_f16(cu[mi][ni], af[mi][0], af[mi][1], af[mi][2], af[mi][3], bu0, bu1);
                }
            }
        }
    }

    #pragma unroll
    for (int mi = 0; mi < 4; mi++) {
        int r0 = m0 + wm * 64 + mi * 16 + grp;
        int r1 = r0 + 8;
        float w0 = 1.f, w1 = 1.f;
        if (routed) {
            if (r0 < M) w0 = g_wgt[e * T_TOK + r0];
            if (r1 < M) w1 = g_wgt[e * T_TOK + r1];
        }
        #pragma unroll
        for (int ni = 0; ni < 4; ni++) {
            int col = n0 + wn * 32 + ni * 8 + tg * 2;
            if (r0 < M) {
                uint32_t v = h2pack(silu_f(cg[mi][ni][0]) * cu[mi][ni][0] * w0,
                                    silu_f(cg[mi][ni][1]) * cu[mi][ni][1] * w0);
                *(uint32_t*)(Act + (size_t)r0 * NS + col) = v;
            }
            if (r1 < M) {
                uint32_t v = h2pack(silu_f(cg[mi][ni][2]) * cu[mi][ni][2] * w1,
                                    silu_f(cg[mi][ni][3]) * cu[mi][ni][3] * w1);
                *(uint32_t*)(Act + (size_t)r1 * NS + col) = v;
            }
        }
    }
}

// ---------------------------------------------------------------------------
// Down-proj fp16 MMA v3: B staged as fp16 [k][n] (144B rows), ldmatrix.trans
// for B fragments. Block 128x64, BK=32, 4 warps (2m x 2n), warp 64x32.
// A: cp.async fp16. B: LDG.128 fp32 -> cvt -> STS.64 fp16 (post-MMA).
// ---------------------------------------------------------------------------
__global__ __launch_bounds__(128, 4)
void k_down(const float* __restrict__ w_down,
            const float* __restrict__ ws_down)
{
    extern __shared__ uint32_t sm[];
    const int z = blockIdx.z;
    const bool routed = z < E_NUM;
    const int e = routed ? z : 0;
    const int M = routed ? g_cnt[e] : T_TOK;
    const int m0 = blockIdx.y * 128;
    if (m0 >= M) return;
    const int n0 = blockIdx.x * 64;
    const int koff = routed ? 0 : (z - E_NUM) * 512;
    const __half* __restrict__ A = routed ? g_act + (size_t)e * T_TOK * I_DIM : g_sact;
    const int AS = routed ? I_DIM : IS_DIM;
    const float* __restrict__ B = routed ? w_down + (size_t)e * I_DIM * H_DIM
                                         : ws_down + (size_t)koff * H_DIM;
    float* __restrict__ Dst = routed ? g_dact + (size_t)e * T_TOK * H_DIM
                                     : g_sds[z - E_NUM];
    const int N = H_DIM;

    const uint32_t sb = smem_u32(sm);
    const int tid = threadIdx.x;
    const int warp = tid >> 5, lane = tid & 31;
    const int wm = warp & 1, wn = warp >> 1;
    const int grp = lane >> 2, tg = lane & 3;

    // A cp.async: 512 units, 4/thread
    const __half* aSrc[4];
    uint32_t aDst[4], aSz[4];
    #pragma unroll
    for (int u = 0; u < 4; u++) {
        int idx = tid + u * 128;
        int am = idx >> 2, ak = idx & 3;
        int gm = m0 + am;
        bool ok = gm < M;
        aSrc[u] = A + (size_t)(ok ? gm : 0) * AS + koff + ak * 8;
        aDst[u] = (uint32_t)(am * 80 + ak * 16);
        aSz[u] = ok ? 16u : 0u;
    }
    // B: LDG fp32 32 rows x 16 float4-units = 512 units, 4/thread
    const float* bSrc[4];
    uint32_t bDst[4];
    #pragma unroll
    for (int u = 0; u < 4; u++) {
        int idx = tid + u * 128;
        int bk = idx >> 4, bc = idx & 15;
        bSrc[u] = B + (size_t)bk * N + n0 + bc * 4;
        bDst[u] = (uint32_t)(10240 + bk * 144 + bc * 8);
    }

    // A ldmatrix offsets (tiles m0k0, m8k0, m0k8, m8k8)
    uint32_t lmoff[4];
    {
        int lr = (lane & 7) + ((lane >> 3) & 1) * 8;
        int lk = lane >> 4;
        #pragma unroll
        for (int mi = 0; mi < 4; mi++)
            lmoff[mi] = (uint32_t)((wm * 64 + mi * 16 + lr) * 80 + lk * 16);
    }
    // B ldmatrix.trans per-lane base: tiles (k0,n0),(k8,n0),(k0,n8),(k8,n8)
    uint32_t lmB;
    {
        int kr = (lane & 7) + ((lane >> 3) & 1) * 8;
        int nc = (lane >> 4) * 8;
        lmB = (uint32_t)(10240 + kr * 144 + (wn * 32 + nc) * 2);
    }

    const int NC = 512 / 32;  // 16
    // prologue chunk 0
    #pragma unroll
    for (int u = 0; u < 4; u++) CP16(sb + aDst[u], aSrc[u], aSz[u]);
    CP_COMMIT();
    #pragma unroll
    for (int u = 0; u < 4; u++) {
        float4 v = *(const float4*)(bSrc[u]);
        *(uint2*)((char*)sm + bDst[u]) = make_uint2(h2pack(v.x, v.y), h2pack(v.z, v.w));
    }

    float acc[4][4][4];
    #pragma unroll
    for (int mi = 0; mi < 4; mi++)
        #pragma unroll
        for (int ni = 0; ni < 4; ni++)
            #pragma unroll
            for (int q = 0; q < 4; q++) acc[mi][ni][q] = 0.f;

    for (int c = 0; c < NC; c++) {
        CP_WAIT0();
        __syncthreads();
        float4 rb[4];
        const bool more = (c + 1) < NC;
        if (more) {
            int c1 = c + 1;
            uint32_t st = sb + (c1 & 1) * DOWN_STAGE_B;
            #pragma unroll
            for (int u = 0; u < 4; u++) CP16(st + aDst[u], aSrc[u] + c1 * 32, aSz[u]);
            CP_COMMIT();
            #pragma unroll
            for (int u = 0; u < 4; u++)
                rb[u] = *(const float4*)(bSrc[u] + (size_t)c1 * 32 * N);
        } else {
            CP_COMMIT();
        }
        const uint32_t sbase = sb + (c & 1) * DOWN_STAGE_B;
        #pragma unroll
        for (int ks = 0; ks < 2; ks++) {
            uint32_t af[4][4];
            #pragma unroll
            for (int mi = 0; mi < 4; mi++)
                ldm_x4(af[mi], sbase + lmoff[mi] + ks * 32);
            #pragma unroll
            for (int p = 0; p < 2; p++) {
                uint32_t br[4];
                ldm_x4t(br, sbase + lmB + ks * 2304 + p * 32);
                #pragma unroll
                for (int mi = 0; mi < 4; mi++) {
                    mma_f16(acc[mi][2 * p],     af[mi][0], af[mi][1], af[mi][2], af[mi][3], br[0], br[1]);
                    mma_f16(acc[mi][2 * p + 1], af[mi][0], af[mi][1], af[mi][2], af[mi][3], br[2], br[3]);
                }
            }
        }
        if (more) {
            char* st = (char*)sm + ((c + 1) & 1) * DOWN_STAGE_B;
            #pragma unroll
            for (int u = 0; u < 4; u++)
                *(uint2*)(st + bDst[u]) =
                    make_uint2(h2pack(rb[u].x, rb[u].y), h2pack(rb[u].z, rb[u].w));
        }
    }

    // epilogue: plain stores to staging
    #pragma unroll
    for (int mi = 0; mi < 4; mi++) {
        int r0 = m0 + wm * 64 + mi * 16 + grp;
        int r1 = r0 + 8;
        bool ok0 = r0 < M, ok1 = r1 < M;
        #pragma unroll
        for (int ni = 0; ni < 4; ni++) {
            int col = n0 + wn * 32 + ni * 8 + tg * 2;
            if (ok0) {
                float2 v = make_float2(acc[mi][ni][0], acc[mi][ni][1]);
                *(float2*)(Dst + (size_t)r0 * N + col) = v;
            }
            if (ok1) {
                float2 v = make_float2(acc[mi][ni][2], acc[mi][ni][3]);
                *(float2*)(Dst + (size_t)r1 * N + col) = v;
            }
        }
    }
}

// ---------------------------------------------------------------------------
// Final gather-reduce: out[t] = sum_{i<8} g_dact[pos_i] + sum_{s<4} g_sds[s][t]
// ---------------------------------------------------------------------------
__global__ __launch_bounds__(256) void k_reduce(float* __restrict__ out) {
    __shared__ int pos[TOPK];
    const int t = blockIdx.x;
    if (threadIdx.x < TOPK) pos[threadIdx.x] = g_pos[t * TOPK + threadIdx.x];
    __syncthreads();
    const int h = threadIdx.x * 4;
    float4 s = *(const float4*)(&g_sds[0][(size_t)t * H_DIM + h]);
    #pragma unroll
    for (int q = 1; q < 4; q++) {
        float4 v = *(const float4*)(&g_sds[q][(size_t)t * H_DIM + h]);
        s.x += v.x; s.y += v.y; s.z += v.z; s.w += v.w;
    }
    #pragma unroll
    for (int i = 0; i < TOPK; i++) {
        float4 v = *(const float4*)(g_dact + (size_t)pos[i] * H_DIM + h);
        s.x += v.x; s.y += v.y; s.z += v.z; s.w += v.w;
    }
    *(float4*)(out + (size_t)t * H_DIM + h) = s;
}

// ---------------------------------------------------------------------------
extern "C" void kernel_launch(void* const* d_in, const int* in_sizes, int n_in,
                              void* d_out, int out_size)
{
    const float* x       = (const float*)d_in[0];
    const float* gate_w  = (const float*)d_in[1];
    const float* e_bias  = (const float*)d_in[2];
    const float* w_gate  = (const float*)d_in[3];
    const float* w_up    = (const float*)d_in[4];
    const float* w_down  = (const float*)d_in[5];
    const float* ws_gate = (const float*)d_in[6];
    const float* ws_up   = (const float*)d_in[7];
    const float* ws_down = (const float*)d_in[8];
    float* out = (float*)d_out;

    static bool attr_done = false;
    if (!attr_done) {
        cudaFuncSetAttribute(k_dual, cudaFuncAttributeMaxDynamicSharedMemorySize, DUAL_SMEM);
        cudaFuncSetAttribute(k_down, cudaFuncAttributeMaxDynamicSharedMemorySize, DOWN_SMEM);
        attr_done = true;
    }

    k_zero<<<1, 32>>>();
    k_gate_route<<<T_TOK, 256>>>(x, gate_w, e_bias);
    // dual GEMMs (R13): routed z=0..31, shared z=32..35
    k_dual<<<dim3(8, 8, E_NUM + 4), 128, DUAL_SMEM>>>(w_gate, w_up, ws_gate, ws_up);
    // down GEMMs: N-tile 64, fp16-B + ldmatrix.trans
    k_down<<<dim3(16, 8, E_NUM + 4), 128, DOWN_SMEM>>>(w_down, ws_down);
    k_reduce<<<T_TOK, 256>>>(out);
}

// round 16
// speedup vs baseline: 1.0657x; 1.0274x over previous
#include <cuda_runtime.h>
#include <cuda_fp16.h>
#include <math.h>
#include <stdint.h>

#define T_TOK 1024
#define H_DIM 1024
#define E_NUM 32
#define I_DIM 512
#define IS_DIM 2048
#define NGROUP 8
#define GSIZE 4
#define TOPKG 4
#define TOPK 8
#define RSCALE 2.5f

// Scratch: activations stored as fp16
__device__ __half g_xh[(size_t)T_TOK * H_DIM];
__device__ __half g_act[(size_t)E_NUM * T_TOK * I_DIM];
__device__ __half g_sact[(size_t)T_TOK * IS_DIM];
__device__ float g_dact[(size_t)E_NUM * T_TOK * H_DIM];   // routed down staging
__device__ float g_sds[4][(size_t)T_TOK * H_DIM];         // shared split-K staging
__device__ int   g_cnt[E_NUM];                            // zeroed at end of k_reduce
__device__ int   g_tok[E_NUM * T_TOK];
__device__ float g_wgt[E_NUM * T_TOK];
__device__ int   g_pos[T_TOK * TOPK];

__device__ __forceinline__ float silu_f(float v) { return v / (1.f + expf(-v)); }

__device__ __forceinline__ uint32_t h2pack(float a, float b) {
    __half2 h = __floats2half2_rn(a, b);
    return *reinterpret_cast<uint32_t*>(&h);
}

__device__ __forceinline__ uint32_t smem_u32(const void* p) {
    uint32_t a;
    asm("{ .reg .u64 t; cvta.to.shared.u64 t, %1; cvt.u32.u64 %0, t; }" : "=r"(a) : "l"(p));
    return a;
}

__device__ __forceinline__ void mma_f16(float* c,
                                        uint32_t a0, uint32_t a1, uint32_t a2, uint32_t a3,
                                        uint32_t b0, uint32_t b1)
{
    asm volatile(
        "mma.sync.aligned.m16n8k16.row.col.f32.f16.f16.f32 "
        "{%0,%1,%2,%3}, {%4,%5,%6,%7}, {%8,%9}, {%0,%1,%2,%3};\n"
        : "+f"(c[0]), "+f"(c[1]), "+f"(c[2]), "+f"(c[3])
        : "r"(a0), "r"(a1), "r"(a2), "r"(a3), "r"(b0), "r"(b1));
}

__device__ __forceinline__ void ldm_x4(uint32_t* r, uint32_t addr) {
    asm volatile("ldmatrix.sync.aligned.m8n8.x4.shared.b16 {%0,%1,%2,%3}, [%4];"
        : "=r"(r[0]), "=r"(r[1]), "=r"(r[2]), "=r"(r[3]) : "r"(addr));
}

#define CP16(dst, src, sz) \
    asm volatile("cp.async.cg.shared.global [%0], [%1], 16, %2;" \
                 :: "r"(dst), "l"(src), "r"(sz) : "memory")
#define CP_COMMIT() asm volatile("cp.async.commit_group;" ::: "memory")
#define CP_WAIT0()  asm volatile("cp.async.wait_group 0;" ::: "memory")

// ---------------------------------------------------------------------------
// Gate GEMV + routing + gather, tiled 8 tokens/block (gate_w read once per 8
// tokens). Also converts the 8 x rows to fp16.
// ---------------------------------------------------------------------------
__global__ __launch_bounds__(256) void k_gate_route(
    const float* __restrict__ x,
    const float* __restrict__ gate_w,
    const float* __restrict__ e_bias)
{
    __shared__ float s_x[8][H_DIM];
    __shared__ float s_logit[8][E_NUM];
    const int t0 = blockIdx.x * 8;
    const int tid = threadIdx.x;
    const int warp = tid >> 5, lane = tid & 31;

    // load 8 token rows into smem + convert to fp16
    #pragma unroll
    for (int u = 0; u < 8; u++) {
        int idx = tid + u * 256;            // 2048 float4 units
        int tt = idx >> 8, c4 = idx & 255;
        float4 v = ((const float4*)(x + (size_t)(t0 + tt) * H_DIM))[c4];
        *(float4*)&s_x[tt][c4 * 4] = v;
        ((uint2*)(g_xh + (size_t)(t0 + tt) * H_DIM))[c4] =
            make_uint2(h2pack(v.x, v.y), h2pack(v.z, v.w));
    }
    __syncthreads();

    // each warp: 4 experts, 8-token dot products
    for (int e = warp; e < E_NUM; e += 8) {
        const float* gw = gate_w + (size_t)e * H_DIM;
        float acc[8];
        #pragma unroll
        for (int t = 0; t < 8; t++) acc[t] = 0.f;
        for (int k = lane; k < H_DIM; k += 32) {
            float g = gw[k];
            #pragma unroll
            for (int t = 0; t < 8; t++) acc[t] += g * s_x[t][k];
        }
        #pragma unroll
        for (int t = 0; t < 8; t++) {
            #pragma unroll
            for (int o = 16; o; o >>= 1)
                acc[t] += __shfl_xor_sync(0xffffffffu, acc[t], o);
        }
        if (lane == 0) {
            #pragma unroll
            for (int t = 0; t < 8; t++) s_logit[t][e] = acc[t];
        }
    }
    __syncthreads();
    if (tid >= 8) return;
    const int t = t0 + tid;

    float scores[E_NUM], swb[E_NUM];
    for (int e = 0; e < E_NUM; e++) {
        float sc = 1.f / (1.f + expf(-s_logit[tid][e]));
        scores[e] = sc;
        swb[e] = sc + e_bias[e];
    }
    float gs[NGROUP];
    for (int g = 0; g < NGROUP; g++) {
        float m1 = -1e30f, m2 = -1e30f;
        for (int j = 0; j < GSIZE; j++) {
            float v = swb[g * GSIZE + j];
            if (v > m1) { m2 = m1; m1 = v; }
            else if (v > m2) m2 = v;
        }
        gs[g] = m1 + m2;
    }
    bool gsel[NGROUP] = {false};
    for (int it = 0; it < TOPKG; it++) {
        int bi = 0; float bv = -1e30f;
        for (int g = 0; g < NGROUP; g++)
            if (!gsel[g] && gs[g] > bv) { bv = gs[g]; bi = g; }
        gsel[bi] = true;
    }
    float val[E_NUM];
    for (int e = 0; e < E_NUM; e++) val[e] = gsel[e / GSIZE] ? swb[e] : 0.f;
    bool taken[E_NUM] = {false};
    int sel[TOPK];
    float denom = 0.f;
    for (int it = 0; it < TOPK; it++) {
        int bi = 0; float bv = -1e30f;
        for (int e = 0; e < E_NUM; e++)
            if (!taken[e] && val[e] > bv) { bv = val[e]; bi = e; }
        taken[bi] = true; sel[it] = bi; denom += scores[bi];
    }
    float inv = RSCALE / (denom + 1e-20f);
    for (int it = 0; it < TOPK; it++) {
        int e = sel[it];
        int slot = atomicAdd(&g_cnt[e], 1);
        g_tok[e * T_TOK + slot] = t;
        g_wgt[e * T_TOK + slot] = scores[e] * inv;
        g_pos[t * TOPK + it] = e * T_TOK + slot;
    }
}

// ---------------------------------------------------------------------------
// DUAL smem stage (words), BK=32 (exact R13):
//   A fp16 128x20 @0 | Bg fp32 32x64 swizzled @2560 | Bu @4608
// Stage = 6656 w = 26624 B; 2 stages (3 CTAs/SM).
// DOWN stage: A fp16 128x20 @0 | B fp32 32x64 swizzled @2560
// Stage = 4608 w = 18432 B; 2 stages (4 CTAs/SM).
// B swizzle: phys_chunk = bc ^ (((bk>>1)&3)<<1).
// ---------------------------------------------------------------------------
#define DUAL_STAGE_W 6656
#define DUAL_STAGE_B 26624
#define DUAL_SMEM (2 * DUAL_STAGE_B)
#define DOWN_STAGE_W 4608
#define DOWN_STAGE_B 18432
#define DOWN_SMEM (2 * DOWN_STAGE_B)

// ---------------------------------------------------------------------------
// Dual fp16 MMA GEMM (exact R13): act = silu(X@Wg)*(X@Wu) [* combine]
// Block 128x64, BK=32, 4 warps (2m x 2n), warp 64x32 dual, ldmatrix A.
// ---------------------------------------------------------------------------
__global__ __launch_bounds__(128, 3)
void k_dual(const float* __restrict__ w_gate,
            const float* __restrict__ w_up,
            const float* __restrict__ ws_gate,
            const float* __restrict__ ws_up)
{
    extern __shared__ uint32_t sm[];
    const int z = blockIdx.z;
    const bool routed = z < E_NUM;
    const int e = routed ? z : 0;
    const int M = routed ? g_cnt[e] : T_TOK;
    const int m0 = blockIdx.y * 128;
    if (m0 >= M) return;
    const int NS = routed ? I_DIM : IS_DIM;
    const int n0 = routed ? blockIdx.x * 64
                          : (z - E_NUM) * 512 + blockIdx.x * 64;
    const float* __restrict__ Wg = routed ? w_gate + (size_t)e * H_DIM * I_DIM : ws_gate;
    const float* __restrict__ Wu = routed ? w_up   + (size_t)e * H_DIM * I_DIM : ws_up;
    __half* __restrict__ Act = routed ? g_act + (size_t)e * T_TOK * I_DIM : g_sact;

    const uint32_t sb = smem_u32(sm);
    const int tid = threadIdx.x;
    const int warp = tid >> 5, lane = tid & 31;
    const int wm = warp & 1, wn = warp >> 1;
    const int grp = lane >> 2, tg = lane & 3;

    const __half* aSrc[4];
    uint32_t aDst[4], aSz[4];
    #pragma unroll
    for (int u = 0; u < 4; u++) {
        int idx = tid + u * 128;
        int am = idx >> 2, ak = idx & 3;
        int gm = m0 + am;
        bool ok = gm < M;
        int srow = ok ? (routed ? g_tok[e * T_TOK + gm] : gm) : 0;
        aSrc[u] = g_xh + (size_t)srow * H_DIM + ak * 8;
        aDst[u] = (uint32_t)(am * 80 + ak * 16);
        aSz[u] = ok ? 16u : 0u;
    }
    const float* gSrc[4];
    const float* uSrc[4];
    uint32_t bDst[4];
    #pragma unroll
    for (int u = 0; u < 4; u++) {
        int idx = tid + u * 128;
        int bk = idx >> 4, bc = idx & 15;
        int cph = bc ^ (((bk >> 1) & 3) << 1);
        gSrc[u] = Wg + (size_t)bk * NS + n0 + bc * 4;
        uSrc[u] = Wu + (size_t)bk * NS + n0 + bc * 4;
        bDst[u] = (uint32_t)((2560 + bk * 64 + cph * 4) * 4);
    }

    uint32_t lmoff[4];
    {
        int lr = (lane & 7) + ((lane >> 3) & 1) * 8;
        int lk = lane >> 4;
        #pragma unroll
        for (int mi = 0; mi < 4; mi++)
            lmoff[mi] = (uint32_t)((wm * 64 + mi * 16 + lr) * 80 + lk * 16);
    }
    int bwv[4];
    #pragma unroll
    for (int ni = 0; ni < 4; ni++) {
        int n = wn * 32 + ni * 8 + grp;
        int cph = (n >> 2) ^ (tg << 1);
        bwv[ni] = 2560 + tg * 128 + cph * 4 + (n & 3);
    }

    const int NC = H_DIM / 32;  // 32
    #pragma unroll
    for (int u = 0; u < 4; u++) {
        CP16(sb + aDst[u], aSrc[u], aSz[u]);
        CP16(sb + bDst[u],        gSrc[u], 16u);
        CP16(sb + bDst[u] + 8192, uSrc[u], 16u);
    }
    CP_COMMIT();

    float cg[4][4][4], cu[4][4][4];
    #pragma unroll
    for (int mi = 0; mi < 4; mi++)
        #pragma unroll
        for (int ni = 0; ni < 4; ni++)
            #pragma unroll
            for (int q = 0; q < 4; q++) { cg[mi][ni][q] = 0.f; cu[mi][ni][q] = 0.f; }

    for (int c = 0; c < NC; c++) {
        CP_WAIT0();
        __syncthreads();
        if (c + 1 < NC) {
            int c1 = c + 1;
            uint32_t st = sb + (c1 & 1) * DUAL_STAGE_B;
            #pragma unroll
            for (int u = 0; u < 4; u++) {
                CP16(st + aDst[u], aSrc[u] + c1 * 32, aSz[u]);
                CP16(st + bDst[u],        gSrc[u] + (size_t)c1 * 32 * NS, 16u);
                CP16(st + bDst[u] + 8192, uSrc[u] + (size_t)c1 * 32 * NS, 16u);
            }
            CP_COMMIT();
        }
        const uint32_t sbase = sb + (c & 1) * DUAL_STAGE_B;
        const float* Sf = (const float*)(sm + (c & 1) * DUAL_STAGE_W);
        #pragma unroll
        for (int ks = 0; ks < 2; ks++) {
            uint32_t af[4][4];
            #pragma unroll
            for (int mi = 0; mi < 4; mi++)
                ldm_x4(af[mi], sbase + lmoff[mi] + ks * 32);
            #pragma unroll
            for (int ni = 0; ni < 4; ni++) {
                const int w = bwv[ni] + ks * 1024;
                uint32_t bg0 = h2pack(Sf[w],        Sf[w + 64]);
                uint32_t bg1 = h2pack(Sf[w + 512],  Sf[w + 576]);
                uint32_t bu0 = h2pack(Sf[w + 2048], Sf[w + 2112]);
                uint32_t bu1 = h2pack(Sf[w + 2560], Sf[w + 2624]);
                #pragma unroll
                for (int mi = 0; mi < 4; mi++) {
                    mma_f16(cg[mi][ni], af[mi][0], af[mi][1], af[mi][2], af[mi][3], bg0, bg1);
                    mma_f16(cu[mi][ni], af[mi][0], af[mi][1], af[mi][2], af[mi][3], bu0, bu1);
                }
            }
        }
    }

    #pragma unroll
    for (int mi = 0; mi < 4; mi++) {
        int r0 = m0 + wm * 64 + mi * 16 + grp;
        int r1 = r0 + 8;
        float w0 = 1.f, w1 = 1.f;
        if (routed) {
            if (r0 < M) w0 = g_wgt[e * T_TOK + r0];
            if (r1 < M) w1 = g_wgt[e * T_TOK + r1];
        }
        #pragma unroll
        for (int ni = 0; ni < 4; ni++) {
            int col = n0 + wn * 32 + ni * 8 + tg * 2;
            if (r0 < M) {
                uint32_t v = h2pack(silu_f(cg[mi][ni][0]) * cu[mi][ni][0] * w0,
                                    silu_f(cg[mi][ni][1]) * cu[mi][ni][1] * w0);
                *(uint32_t*)(Act + (size_t)r0 * NS + col) = v;
            }
            if (r1 < M) {
                uint32_t v = h2pack(silu_f(cg[mi][ni][2]) * cu[mi][ni][2] * w1,
                                    silu_f(cg[mi][ni][3]) * cu[mi][ni][3] * w1);
                *(uint32_t*)(Act + (size_t)r1 * NS + col) = v;
            }
        }
    }
}

// ---------------------------------------------------------------------------
// Down-proj fp16 MMA (exact R13): N-tile 64, 4 CTAs/SM.
// Block 128x64, BK=32, 4 warps (2m x 2n), warp 64x32, ldmatrix A, acc=64.
// ---------------------------------------------------------------------------
__global__ __launch_bounds__(128, 4)
void k_down(const float* __restrict__ w_down,
            const float* __restrict__ ws_down)
{
    extern __shared__ uint32_t sm[];
    const int z = blockIdx.z;
    const bool routed = z < E_NUM;
    const int e = routed ? z : 0;
    const int M = routed ? g_cnt[e] : T_TOK;
    const int m0 = blockIdx.y * 128;
    if (m0 >= M) return;
    const int n0 = blockIdx.x * 64;
    const int koff = routed ? 0 : (z - E_NUM) * 512;
    const __half* __restrict__ A = routed ? g_act + (size_t)e * T_TOK * I_DIM : g_sact;
    const int AS = routed ? I_DIM : IS_DIM;
    const float* __restrict__ B = routed ? w_down + (size_t)e * I_DIM * H_DIM
                                         : ws_down + (size_t)koff * H_DIM;
    float* __restrict__ Dst = routed ? g_dact + (size_t)e * T_TOK * H_DIM
                                     : g_sds[z - E_NUM];
    const int N = H_DIM;

    const uint32_t sb = smem_u32(sm);
    const int tid = threadIdx.x;
    const int warp = tid >> 5, lane = tid & 31;
    const int wm = warp & 1, wn = warp >> 1;
    const int grp = lane >> 2, tg = lane & 3;

    const __half* aSrc[4];
    uint32_t aDst[4], aSz[4];
    #pragma unroll
    for (int u = 0; u < 4; u++) {
        int idx = tid + u * 128;
        int am = idx >> 2, ak = idx & 3;
        int gm = m0 + am;
        bool ok = gm < M;
        aSrc[u] = A + (size_t)(ok ? gm : 0) * AS + koff + ak * 8;
        aDst[u] = (uint32_t)(am * 80 + ak * 16);
        aSz[u] = ok ? 16u : 0u;
    }
    const float* bSrc[4];
    uint32_t bDst[4];
    #pragma unroll
    for (int u = 0; u < 4; u++) {
        int idx = tid + u * 128;
        int bk = idx >> 4, bc = idx & 15;
        int cph = bc ^ (((bk >> 1) & 3) << 1);
        bSrc[u] = B + (size_t)bk * N + n0 + bc * 4;
        bDst[u] = (uint32_t)((2560 + bk * 64 + cph * 4) * 4);
    }

    uint32_t lmoff[4];
    {
        int lr = (lane & 7) + ((lane >> 3) & 1) * 8;
        int lk = lane >> 4;
        #pragma unroll
        for (int mi = 0; mi < 4; mi++)
            lmoff[mi] = (uint32_t)((wm * 64 + mi * 16 + lr) * 80 + lk * 16);
    }
    int bwv[4];
    #pragma unroll
    for (int ni = 0; ni < 4; ni++) {
        int n = wn * 32 + ni * 8 + grp;
        int cph = (n >> 2) ^ (tg << 1);
        bwv[ni] = 2560 + tg * 128 + cph * 4 + (n & 3);
    }

    const int NC = 512 / 32;  // 16
    #pragma unroll
    for (int u = 0; u < 4; u++) {
        CP16(sb + aDst[u], aSrc[u], aSz[u]);
        CP16(sb + bDst[u], bSrc[u], 16u);
    }
    CP_COMMIT();

    float acc[4][4][4];
    #pragma unroll
    for (int mi = 0; mi < 4; mi++)
        #pragma unroll
        for (int ni = 0; ni < 4; ni++)
            #pragma unroll
            for (int q = 0; q < 4; q++) acc[mi][ni][q] = 0.f;

    for (int c = 0; c < NC; c++) {
        CP_WAIT0();
        __syncthreads();
        if (c + 1 < NC) {
            int c1 = c + 1;
            uint32_t st = sb + (c1 & 1) * DOWN_STAGE_B;
            #pragma unroll
            for (int u = 0; u < 4; u++) {
                CP16(st + aDst[u], aSrc[u] + c1 * 32, aSz[u]);
                CP16(st + bDst[u], bSrc[u] + (size_t)c1 * 32 * N, 16u);
            }
            CP_COMMIT();
        }
        const uint32_t sbase = sb + (c & 1) * DOWN_STAGE_B;
        const float* Sf = (const float*)(sm + (c & 1) * DOWN_STAGE_W);
        #pragma unroll
        for (int ks = 0; ks < 2; ks++) {
            uint32_t af[4][4];
            #pragma unroll
            for (int mi = 0; mi < 4; mi++)
                ldm_x4(af[mi], sbase + lmoff[mi] + ks * 32);
            #pragma unroll
            for (int ni = 0; ni < 4; ni++) {
                const int w = bwv[ni] + ks * 1024;
                uint32_t b0 = h2pack(Sf[w],       Sf[w + 64]);
                uint32_t b1 = h2pack(Sf[w + 512], Sf[w + 576]);
                #pragma unroll
                for (int mi = 0; mi < 4; mi++)
                    mma_f16(acc[mi][ni], af[mi][0], af[mi][1], af[mi][2], af[mi][3], b0, b1);
            }
        }
    }

    #pragma unroll
    for (int mi = 0; mi < 4; mi++) {
        int r0 = m0 + wm * 64 + mi * 16 + grp;
        int r1 = r0 + 8;
        bool ok0 = r0 < M, ok1 = r1 < M;
        #pragma unroll
        for (int ni = 0; ni < 4; ni++) {
            int col = n0 + wn * 32 + ni * 8 + tg * 2;
            if (ok0) {
                float2 v = make_float2(acc[mi][ni][0], acc[mi][ni][1]);
                *(float2*)(Dst + (size_t)r0 * N + col) = v;
            }
            if (ok1) {
                float2 v = make_float2(acc[mi][ni][2], acc[mi][ni][3]);
                *(float2*)(Dst + (size_t)r1 * N + col) = v;
            }
        }
    }
}

// ---------------------------------------------------------------------------
// Final gather-reduce: out[t] = sum_{i<8} g_dact[pos_i] + sum_{s<4} g_sds[s][t]
// Also re-zeroes g_cnt for the next kernel_launch invocation.
// ---------------------------------------------------------------------------
__global__ __launch_bounds__(256) void k_reduce(float* __restrict__ out) {
    __shared__ int pos[TOPK];
    const int t = blockIdx.x;
    if (blockIdx.x == 0 && threadIdx.x < E_NUM) g_cnt[threadIdx.x] = 0;
    if (threadIdx.x < TOPK) pos[threadIdx.x] = g_pos[t * TOPK + threadIdx.x];
    __syncthreads();
    const int h = threadIdx.x * 4;
    float4 s = *(const float4*)(&g_sds[0][(size_t)t * H_DIM + h]);
    #pragma unroll
    for (int q = 1; q < 4; q++) {
        float4 v = *(const float4*)(&g_sds[q][(size_t)t * H_DIM + h]);
        s.x += v.x; s.y += v.y; s.z += v.z; s.w += v.w;
    }
    #pragma unroll
    for (int i = 0; i < TOPK; i++) {
        float4 v = *(const float4*)(g_dact + (size_t)pos[i] * H_DIM + h);
        s.x += v.x; s.y += v.y; s.z += v.z; s.w += v.w;
    }
    *(float4*)(out + (size_t)t * H_DIM + h) = s;
}

// ---------------------------------------------------------------------------
extern "C" void kernel_launch(void* const* d_in, const int* in_sizes, int n_in,
                              void* d_out, int out_size)
{
    const float* x       = (const float*)d_in[0];
    const float* gate_w  = (const float*)d_in[1];
    const float* e_bias  = (const float*)d_in[2];
    const float* w_gate  = (const float*)d_in[3];
    const float* w_up    = (const float*)d_in[4];
    const float* w_down  = (const float*)d_in[5];
    const float* ws_gate = (const float*)d_in[6];
    const float* ws_up   = (const float*)d_in[7];
    const float* ws_down = (const float*)d_in[8];
    float* out = (float*)d_out;

    static bool attr_done = false;
    if (!attr_done) {
        cudaFuncSetAttribute(k_dual, cudaFuncAttributeMaxDynamicSharedMemorySize, DUAL_SMEM);
        cudaFuncSetAttribute(k_down, cudaFuncAttributeMaxDynamicSharedMemorySize, DOWN_SMEM);
        attr_done = true;
    }

    // g_cnt is zero on first call (static init) and re-zeroed by k_reduce.
    k_gate_route<<<T_TOK / 8, 256>>>(x, gate_w, e_bias);
    // dual GEMMs (R13): routed z=0..31, shared z=32..35
    k_dual<<<dim3(8, 8, E_NUM + 4), 128, DUAL_SMEM>>>(w_gate, w_up, ws_gate, ws_up);
    // down GEMMs (R13): N-tile 64, routed z=0..31, shared split-K z=32..35
    k_down<<<dim3(16, 8, E_NUM + 4), 128, DOWN_SMEM>>>(w_down, ws_down);
    k_reduce<<<T_TOK, 256>>>(out);
}

// round 17
// speedup vs baseline: 1.0672x; 1.0013x over previous
#include <cuda_runtime.h>
#include <cuda_fp16.h>
#include <math.h>
#include <stdint.h>

#define T_TOK 1024
#define H_DIM 1024
#define E_NUM 32
#define I_DIM 512
#define IS_DIM 2048
#define NGROUP 8
#define GSIZE 4
#define TOPKG 4
#define TOPK 8
#define RSCALE 2.5f

// Scratch: activations + down staging stored as fp16
__device__ __half g_xh[(size_t)T_TOK * H_DIM];
__device__ __half g_act[(size_t)E_NUM * T_TOK * I_DIM];
__device__ __half g_sact[(size_t)T_TOK * IS_DIM];
__device__ __half g_dact[(size_t)E_NUM * T_TOK * H_DIM];  // routed down staging (fp16)
__device__ __half g_sds[4][(size_t)T_TOK * H_DIM];        // shared split-K staging (fp16)
__device__ int   g_cnt[E_NUM];                            // zeroed at end of k_reduce
__device__ int   g_tok[E_NUM * T_TOK];
__device__ float g_wgt[E_NUM * T_TOK];
__device__ int   g_pos[T_TOK * TOPK];

__device__ __forceinline__ float silu_f(float v) { return v / (1.f + expf(-v)); }

__device__ __forceinline__ uint32_t h2pack(float a, float b) {
    __half2 h = __floats2half2_rn(a, b);
    return *reinterpret_cast<uint32_t*>(&h);
}

__device__ __forceinline__ uint32_t smem_u32(const void* p) {
    uint32_t a;
    asm("{ .reg .u64 t; cvta.to.shared.u64 t, %1; cvt.u32.u64 %0, t; }" : "=r"(a) : "l"(p));
    return a;
}

__device__ __forceinline__ void mma_f16(float* c,
                                        uint32_t a0, uint32_t a1, uint32_t a2, uint32_t a3,
                                        uint32_t b0, uint32_t b1)
{
    asm volatile(
        "mma.sync.aligned.m16n8k16.row.col.f32.f16.f16.f32 "
        "{%0,%1,%2,%3}, {%4,%5,%6,%7}, {%8,%9}, {%0,%1,%2,%3};\n"
        : "+f"(c[0]), "+f"(c[1]), "+f"(c[2]), "+f"(c[3])
        : "r"(a0), "r"(a1), "r"(a2), "r"(a3), "r"(b0), "r"(b1));
}

__device__ __forceinline__ void ldm_x4(uint32_t* r, uint32_t addr) {
    asm volatile("ldmatrix.sync.aligned.m8n8.x4.shared.b16 {%0,%1,%2,%3}, [%4];"
        : "=r"(r[0]), "=r"(r[1]), "=r"(r[2]), "=r"(r[3]) : "r"(addr));
}

#define CP16(dst, src, sz) \
    asm volatile("cp.async.cg.shared.global [%0], [%1], 16, %2;" \
                 :: "r"(dst), "l"(src), "r"(sz) : "memory")
#define CP_COMMIT() asm volatile("cp.async.commit_group;" ::: "memory")
#define CP_WAIT0()  asm volatile("cp.async.wait_group 0;" ::: "memory")
#define CP_WAIT1()  asm volatile("cp.async.wait_group 1;" ::: "memory")

// ---------------------------------------------------------------------------
// Gate GEMV + routing + gather, tiled 8 tokens/block. Converts x rows to fp16.
// ---------------------------------------------------------------------------
__global__ __launch_bounds__(256) void k_gate_route(
    const float* __restrict__ x,
    const float* __restrict__ gate_w,
    const float* __restrict__ e_bias)
{
    __shared__ float s_x[8][H_DIM];
    __shared__ float s_logit[8][E_NUM];
    const int t0 = blockIdx.x * 8;
    const int tid = threadIdx.x;
    const int warp = tid >> 5, lane = tid & 31;

    #pragma unroll
    for (int u = 0; u < 8; u++) {
        int idx = tid + u * 256;
        int tt = idx >> 8, c4 = idx & 255;
        float4 v = ((const float4*)(x + (size_t)(t0 + tt) * H_DIM))[c4];
        *(float4*)&s_x[tt][c4 * 4] = v;
        ((uint2*)(g_xh + (size_t)(t0 + tt) * H_DIM))[c4] =
            make_uint2(h2pack(v.x, v.y), h2pack(v.z, v.w));
    }
    __syncthreads();

    for (int e = warp; e < E_NUM; e += 8) {
        const float* gw = gate_w + (size_t)e * H_DIM;
        float acc[8];
        #pragma unroll
        for (int t = 0; t < 8; t++) acc[t] = 0.f;
        for (int k = lane; k < H_DIM; k += 32) {
            float g = gw[k];
            #pragma unroll
            for (int t = 0; t < 8; t++) acc[t] += g * s_x[t][k];
        }
        #pragma unroll
        for (int t = 0; t < 8; t++) {
            #pragma unroll
            for (int o = 16; o; o >>= 1)
                acc[t] += __shfl_xor_sync(0xffffffffu, acc[t], o);
        }
        if (lane == 0) {
            #pragma unroll
            for (int t = 0; t < 8; t++) s_logit[t][e] = acc[t];
        }
    }
    __syncthreads();
    if (tid >= 8) return;
    const int t = t0 + tid;

    float scores[E_NUM], swb[E_NUM];
    for (int e = 0; e < E_NUM; e++) {
        float sc = 1.f / (1.f + expf(-s_logit[tid][e]));
        scores[e] = sc;
        swb[e] = sc + e_bias[e];
    }
    float gs[NGROUP];
    for (int g = 0; g < NGROUP; g++) {
        float m1 = -1e30f, m2 = -1e30f;
        for (int j = 0; j < GSIZE; j++) {
            float v = swb[g * GSIZE + j];
            if (v > m1) { m2 = m1; m1 = v; }
            else if (v > m2) m2 = v;
        }
        gs[g] = m1 + m2;
    }
    bool gsel[NGROUP] = {false};
    for (int it = 0; it < TOPKG; it++) {
        int bi = 0; float bv = -1e30f;
        for (int g = 0; g < NGROUP; g++)
            if (!gsel[g] && gs[g] > bv) { bv = gs[g]; bi = g; }
        gsel[bi] = true;
    }
    float val[E_NUM];
    for (int e = 0; e < E_NUM; e++) val[e] = gsel[e / GSIZE] ? swb[e] : 0.f;
    bool taken[E_NUM] = {false};
    int sel[TOPK];
    float denom = 0.f;
    for (int it = 0; it < TOPK; it++) {
        int bi = 0; float bv = -1e30f;
        for (int e = 0; e < E_NUM; e++)
            if (!taken[e] && val[e] > bv) { bv = val[e]; bi = e; }
        taken[bi] = true; sel[it] = bi; denom += scores[bi];
    }
    float inv = RSCALE / (denom + 1e-20f);
    for (int it = 0; it < TOPK; it++) {
        int e = sel[it];
        int slot = atomicAdd(&g_cnt[e], 1);
        g_tok[e * T_TOK + slot] = t;
        g_wgt[e * T_TOK + slot] = scores[e] * inv;
        g_pos[t * TOPK + it] = e * T_TOK + slot;
    }
}

// ---------------------------------------------------------------------------
// DUAL stage (words), BK=32: A fp16 128x20 @0 | Bg fp32 swz @2560 | Bu @4608
// Stage = 26624 B; 2 stages (3 CTAs/SM).
// DOWN stage: A fp16 128x20 @0 | B fp32 swz @2560. Stage = 18432 B; 3 stages
// (55296 B; 4 CTAs/SM = 221 KB). B swizzle: phys_chunk = bc ^ (((bk>>1)&3)<<1).
// ---------------------------------------------------------------------------
#define DUAL_STAGE_W 6656
#define DUAL_STAGE_B 26624
#define DUAL_SMEM (2 * DUAL_STAGE_B)
#define DOWN_STAGE_W 4608
#define DOWN_STAGE_B 18432
#define DOWN_SMEM (3 * DOWN_STAGE_B)

// ---------------------------------------------------------------------------
// Dual fp16 MMA GEMM (exact R13): act = silu(X@Wg)*(X@Wu) [* combine]
// ---------------------------------------------------------------------------
__global__ __launch_bounds__(128, 3)
void k_dual(const float* __restrict__ w_gate,
            const float* __restrict__ w_up,
            const float* __restrict__ ws_gate,
            const float* __restrict__ ws_up)
{
    extern __shared__ uint32_t sm[];
    const int z = blockIdx.z;
    const bool routed = z < E_NUM;
    const int e = routed ? z : 0;
    const int M = routed ? g_cnt[e] : T_TOK;
    const int m0 = blockIdx.y * 128;
    if (m0 >= M) return;
    const int NS = routed ? I_DIM : IS_DIM;
    const int n0 = routed ? blockIdx.x * 64
                          : (z - E_NUM) * 512 + blockIdx.x * 64;
    const float* __restrict__ Wg = routed ? w_gate + (size_t)e * H_DIM * I_DIM : ws_gate;
    const float* __restrict__ Wu = routed ? w_up   + (size_t)e * H_DIM * I_DIM : ws_up;
    __half* __restrict__ Act = routed ? g_act + (size_t)e * T_TOK * I_DIM : g_sact;

    const uint32_t sb = smem_u32(sm);
    const int tid = threadIdx.x;
    const int warp = tid >> 5, lane = tid & 31;
    const int wm = warp & 1, wn = warp >> 1;
    const int grp = lane >> 2, tg = lane & 3;

    const __half* aSrc[4];
    uint32_t aDst[4], aSz[4];
    #pragma unroll
    for (int u = 0; u < 4; u++) {
        int idx = tid + u * 128;
        int am = idx >> 2, ak = idx & 3;
        int gm = m0 + am;
        bool ok = gm < M;
        int srow = ok ? (routed ? g_tok[e * T_TOK + gm] : gm) : 0;
        aSrc[u] = g_xh + (size_t)srow * H_DIM + ak * 8;
        aDst[u] = (uint32_t)(am * 80 + ak * 16);
        aSz[u] = ok ? 16u : 0u;
    }
    const float* gSrc[4];
    const float* uSrc[4];
    uint32_t bDst[4];
    #pragma unroll
    for (int u = 0; u < 4; u++) {
        int idx = tid + u * 128;
        int bk = idx >> 4, bc = idx & 15;
        int cph = bc ^ (((bk >> 1) & 3) << 1);
        gSrc[u] = Wg + (size_t)bk * NS + n0 + bc * 4;
        uSrc[u] = Wu + (size_t)bk * NS + n0 + bc * 4;
        bDst[u] = (uint32_t)((2560 + bk * 64 + cph * 4) * 4);
    }

    uint32_t lmoff[4];
    {
        int lr = (lane & 7) + ((lane >> 3) & 1) * 8;
        int lk = lane >> 4;
        #pragma unroll
        for (int mi = 0; mi < 4; mi++)
            lmoff[mi] = (uint32_t)((wm * 64 + mi * 16 + lr) * 80 + lk * 16);
    }
    int bwv[4];
    #pragma unroll
    for (int ni = 0; ni < 4; ni++) {
        int n = wn * 32 + ni * 8 + grp;
        int cph = (n >> 2) ^ (tg << 1);
        bwv[ni] = 2560 + tg * 128 + cph * 4 + (n & 3);
    }

    const int NC = H_DIM / 32;  // 32
    #pragma unroll
    for (int u = 0; u < 4; u++) {
        CP16(sb + aDst[u], aSrc[u], aSz[u]);
        CP16(sb + bDst[u],        gSrc[u], 16u);
        CP16(sb + bDst[u] + 8192, uSrc[u], 16u);
    }
    CP_COMMIT();

    float cg[4][4][4], cu[4][4][4];
    #pragma unroll
    for (int mi = 0; mi < 4; mi++)
        #pragma unroll
        for (int ni = 0; ni < 4; ni++)
            #pragma unroll
            for (int q = 0; q < 4; q++) { cg[mi][ni][q] = 0.f; cu[mi][ni][q] = 0.f; }

    for (int c = 0; c < NC; c++) {
        CP_WAIT0();
        __syncthreads();
        if (c + 1 < NC) {
            int c1 = c + 1;
            uint32_t st = sb + (c1 & 1) * DUAL_STAGE_B;
            #pragma unroll
            for (int u = 0; u < 4; u++) {
                CP16(st + aDst[u], aSrc[u] + c1 * 32, aSz[u]);
                CP16(st + bDst[u],        gSrc[u] + (size_t)c1 * 32 * NS, 16u);
                CP16(st + bDst[u] + 8192, uSrc[u] + (size_t)c1 * 32 * NS, 16u);
            }
            CP_COMMIT();
        }
        const uint32_t sbase = sb + (c & 1) * DUAL_STAGE_B;
        const float* Sf = (const float*)(sm + (c & 1) * DUAL_STAGE_W);
        #pragma unroll
        for (int ks = 0; ks < 2; ks++) {
            uint32_t af[4][4];
            #pragma unroll
            for (int mi = 0; mi < 4; mi++)
                ldm_x4(af[mi], sbase + lmoff[mi] + ks * 32);
            #pragma unroll
            for (int ni = 0; ni < 4; ni++) {
                const int w = bwv[ni] + ks * 1024;
                uint32_t bg0 = h2pack(Sf[w],        Sf[w + 64]);
                uint32_t bg1 = h2pack(Sf[w + 512],  Sf[w + 576]);
                uint32_t bu0 = h2pack(Sf[w + 2048], Sf[w + 2112]);
                uint32_t bu1 = h2pack(Sf[w + 2560], Sf[w + 2624]);
                #pragma unroll
                for (int mi = 0; mi < 4; mi++) {
                    mma_f16(cg[mi][ni], af[mi][0], af[mi][1], af[mi][2], af[mi][3], bg0, bg1);
                    mma_f16(cu[mi][ni], af[mi][0], af[mi][1], af[mi][2], af[mi][3], bu0, bu1);
                }
            }
        }
    }

    #pragma unroll
    for (int mi = 0; mi < 4; mi++) {
        int r0 = m0 + wm * 64 + mi * 16 + grp;
        int r1 = r0 + 8;
        float w0 = 1.f, w1 = 1.f;
        if (routed) {
            if (r0 < M) w0 = g_wgt[e * T_TOK + r0];
            if (r1 < M) w1 = g_wgt[e * T_TOK + r1];
        }
        #pragma unroll
        for (int ni = 0; ni < 4; ni++) {
            int col = n0 + wn * 32 + ni * 8 + tg * 2;
            if (r0 < M) {
                uint32_t v = h2pack(silu_f(cg[mi][ni][0]) * cu[mi][ni][0] * w0,
                                    silu_f(cg[mi][ni][1]) * cu[mi][ni][1] * w0);
                *(uint32_t*)(Act + (size_t)r0 * NS + col) = v;
            }
            if (r1 < M) {
                uint32_t v = h2pack(silu_f(cg[mi][ni][2]) * cu[mi][ni][2] * w1,
                                    silu_f(cg[mi][ni][3]) * cu[mi][ni][3] * w1);
                *(uint32_t*)(Act + (size_t)r1 * NS + col) = v;
            }
        }
    }
}

// ---------------------------------------------------------------------------
// Down-proj fp16 MMA: N-tile 64, 4 CTAs/SM, 3-stage pipeline (wait_group 1).
// fp16 staging stores.
// ---------------------------------------------------------------------------
__global__ __launch_bounds__(128, 4)
void k_down(const float* __restrict__ w_down,
            const float* __restrict__ ws_down)
{
    extern __shared__ uint32_t sm[];
    const int z = blockIdx.z;
    const bool routed = z < E_NUM;
    const int e = routed ? z : 0;
    const int M = routed ? g_cnt[e] : T_TOK;
    const int m0 = blockIdx.y * 128;
    if (m0 >= M) return;
    const int n0 = blockIdx.x * 64;
    const int koff = routed ? 0 : (z - E_NUM) * 512;
    const __half* __restrict__ A = routed ? g_act + (size_t)e * T_TOK * I_DIM : g_sact;
    const int AS = routed ? I_DIM : IS_DIM;
    const float* __restrict__ B = routed ? w_down + (size_t)e * I_DIM * H_DIM
                                         : ws_down + (size_t)koff * H_DIM;
    __half* __restrict__ Dst = routed ? g_dact + (size_t)e * T_TOK * H_DIM
                                      : g_sds[z - E_NUM];
    const int N = H_DIM;

    const uint32_t sb = smem_u32(sm);
    const int tid = threadIdx.x;
    const int warp = tid >> 5, lane = tid & 31;
    const int wm = warp & 1, wn = warp >> 1;
    const int grp = lane >> 2, tg = lane & 3;

    const __half* aSrc[4];
    uint32_t aDst[4], aSz[4];
    #pragma unroll
    for (int u = 0; u < 4; u++) {
        int idx = tid + u * 128;
        int am = idx >> 2, ak = idx & 3;
        int gm = m0 + am;
        bool ok = gm < M;
        aSrc[u] = A + (size_t)(ok ? gm : 0) * AS + koff + ak * 8;
        aDst[u] = (uint32_t)(am * 80 + ak * 16);
        aSz[u] = ok ? 16u : 0u;
    }
    const float* bSrc[4];
    uint32_t bDst[4];
    #pragma unroll
    for (int u = 0; u < 4; u++) {
        int idx = tid + u * 128;
        int bk = idx >> 4, bc = idx & 15;
        int cph = bc ^ (((bk >> 1) & 3) << 1);
        bSrc[u] = B + (size_t)bk * N + n0 + bc * 4;
        bDst[u] = (uint32_t)((2560 + bk * 64 + cph * 4) * 4);
    }

    uint32_t lmoff[4];
    {
        int lr = (lane & 7) + ((lane >> 3) & 1) * 8;
        int lk = lane >> 4;
        #pragma unroll
        for (int mi = 0; mi < 4; mi++)
            lmoff[mi] = (uint32_t)((wm * 64 + mi * 16 + lr) * 80 + lk * 16);
    }
    int bwv[4];
    #pragma unroll
    for (int ni = 0; ni < 4; ni++) {
        int n = wn * 32 + ni * 8 + grp;
        int cph = (n >> 2) ^ (tg << 1);
        bwv[ni] = 2560 + tg * 128 + cph * 4 + (n & 3);
    }

    const int NC = 512 / 32;  // 16
    // prologue: stages 0, 1
    #pragma unroll
    for (int p = 0; p < 2; p++) {
        uint32_t st = sb + p * DOWN_STAGE_B;
        #pragma unroll
        for (int u = 0; u < 4; u++) {
            CP16(st + aDst[u], aSrc[u] + p * 32, aSz[u]);
            CP16(st + bDst[u], bSrc[u] + (size_t)p * 32 * N, 16u);
        }
        CP_COMMIT();
    }

    float acc[4][4][4];
    #pragma unroll
    for (int mi = 0; mi < 4; mi++)
        #pragma unroll
        for (int ni = 0; ni < 4; ni++)
            #pragma unroll
            for (int q = 0; q < 4; q++) acc[mi][ni][q] = 0.f;

    for (int c = 0; c < NC; c++) {
        CP_WAIT1();
        __syncthreads();
        if (c + 2 < NC) {
            int c2 = c + 2;
            uint32_t st = sb + (c2 % 3) * DOWN_STAGE_B;
            #pragma unroll
            for (int u = 0; u < 4; u++) {
                CP16(st + aDst[u], aSrc[u] + c2 * 32, aSz[u]);
                CP16(st + bDst[u], bSrc[u] + (size_t)c2 * 32 * N, 16u);
            }
        }
        CP_COMMIT();
        const uint32_t sbase = sb + (c % 3) * DOWN_STAGE_B;
        const float* Sf = (const float*)(sm + (c % 3) * DOWN_STAGE_W);
        #pragma unroll
        for (int ks = 0; ks < 2; ks++) {
            uint32_t af[4][4];
            #pragma unroll
            for (int mi = 0; mi < 4; mi++)
                ldm_x4(af[mi], sbase + lmoff[mi] + ks * 32);
            #pragma unroll
            for (int ni = 0; ni < 4; ni++) {
                const int w = bwv[ni] + ks * 1024;
                uint32_t b0 = h2pack(Sf[w],       Sf[w + 64]);
                uint32_t b1 = h2pack(Sf[w + 512], Sf[w + 576]);
                #pragma unroll
                for (int mi = 0; mi < 4; mi++)
                    mma_f16(acc[mi][ni], af[mi][0], af[mi][1], af[mi][2], af[mi][3], b0, b1);
            }
        }
    }

    // epilogue: fp16 stores to staging
    #pragma unroll
    for (int mi = 0; mi < 4; mi++) {
        int r0 = m0 + wm * 64 + mi * 16 + grp;
        int r1 = r0 + 8;
        bool ok0 = r0 < M, ok1 = r1 < M;
        #pragma unroll
        for (int ni = 0; ni < 4; ni++) {
            int col = n0 + wn * 32 + ni * 8 + tg * 2;
            if (ok0)
                *(uint32_t*)(Dst + (size_t)r0 * N + col) = h2pack(acc[mi][ni][0], acc[mi][ni][1]);
            if (ok1)
                *(uint32_t*)(Dst + (size_t)r1 * N + col) = h2pack(acc[mi][ni][2], acc[mi][ni][3]);
        }
    }
}

// ---------------------------------------------------------------------------
// Final gather-reduce (fp16 staging): out[t] = sum_8 g_dact[pos_i] + sum_4 g_sds
// Also re-zeroes g_cnt for the next invocation.
// ---------------------------------------------------------------------------
__global__ __launch_bounds__(256) void k_reduce(float* __restrict__ out) {
    __shared__ int pos[TOPK];
    const int t = blockIdx.x;
    if (blockIdx.x == 0 && threadIdx.x < E_NUM) g_cnt[threadIdx.x] = 0;
    if (threadIdx.x < TOPK) pos[threadIdx.x] = g_pos[t * TOPK + threadIdx.x];
    __syncthreads();
    const int h = threadIdx.x * 4;
    float2 s01 = make_float2(0.f, 0.f), s23 = make_float2(0.f, 0.f);
    #pragma unroll
    for (int q = 0; q < 4; q++) {
        uint2 v = *(const uint2*)(&g_sds[q][(size_t)t * H_DIM + h]);
        float2 a = __half22float2(*(__half2*)&v.x);
        float2 b = __half22float2(*(__half2*)&v.y);
        s01.x += a.x; s01.y += a.y; s23.x += b.x; s23.y += b.y;
    }
    #pragma unroll
    for (int i = 0; i < TOPK; i++) {
        uint2 v = *(const uint2*)(g_dact + (size_t)pos[i] * H_DIM + h);
        float2 a = __half22float2(*(__half2*)&v.x);
        float2 b = __half22float2(*(__half2*)&v.y);
        s01.x += a.x; s01.y += a.y; s23.x += b.x; s23.y += b.y;
    }
    float4 o = make_float4(s01.x, s01.y, s23.x, s23.y);
    *(float4*)(out + (size_t)t * H_DIM + h) = o;
}

// ---------------------------------------------------------------------------
extern "C" void kernel_launch(void* const* d_in, const int* in_sizes, int n_in,
                              void* d_out, int out_size)
{
    const float* x       = (const float*)d_in[0];
    const float* gate_w  = (const float*)d_in[1];
    const float* e_bias  = (const float*)d_in[2];
    const float* w_gate  = (const float*)d_in[3];
    const float* w_up    = (const float*)d_in[4];
    const float* w_down  = (const float*)d_in[5];
    const float* ws_gate = (const float*)d_in[6];
    const float* ws_up   = (const float*)d_in[7];
    const float* ws_down = (const float*)d_in[8];
    float* out = (float*)d_out;

    static bool attr_done = false;
    if (!attr_done) {
        cudaFuncSetAttribute(k_dual, cudaFuncAttributeMaxDynamicSharedMemorySize, DUAL_SMEM);
        cudaFuncSetAttribute(k_down, cudaFuncAttributeMaxDynamicSharedMemorySize, DOWN_SMEM);
        attr_done = true;
    }

    // g_cnt is zero on first call (static init) and re-zeroed by k_reduce.
    k_gate_route<<<T_TOK / 8, 256>>>(x, gate_w, e_bias);
    k_dual<<<dim3(8, 8, E_NUM + 4), 128, DUAL_SMEM>>>(w_gate, w_up, ws_gate, ws_up);
    k_down<<<dim3(16, 8, E_NUM + 4), 128, DOWN_SMEM>>>(w_down, ws_down);
    k_reduce<<<T_TOK, 256>>>(out);
}